// round 14
// baseline (speedup 1.0000x reference)
#include <cuda_runtime.h>
#include <cuda_bf16.h>
#include <cuda_fp16.h>
#include <math.h>
#include <stdint.h>

// ---------------- problem constants ----------------
#define T_NEW 16
#define HIDDEN 2560
#define INTER 9728
#define NH 32
#define NKV 8
#define HD 128
#define TC 4080
#define TFULL 4096
#define RMS_EPS 1e-6f
#define PROW 20      // half2 words per 32-float k-chunk row (16 + 4 pad)
#define APROW 36     // fp32 pad for pvMMA A
#define VPAD 136

// ---------------- scratch (device globals, no allocs) ----------------
__device__ float g_y[T_NEW * HIDDEN];
__device__ float g_q[T_NEW * NH * HD];
__device__ float g_k[T_NEW * NKV * HD];
__device__ float g_v[T_NEW * NKV * HD];
__device__ float g_scores[NH * T_NEW * TFULL];
__device__ float g_attnout[T_NEW * NH * HD];
__device__ float g_h[T_NEW * HIDDEN];
__device__ float g_y2[T_NEW * HIDDEN];
__device__ float g_gate[T_NEW * INTER];
__device__ float g_up[T_NEW * INTER];

// ---------------- fp16 / tf32 mma helpers ----------------
__device__ __forceinline__ uint32_t h2(float lo, float hi) {
    uint32_t r;
    asm("cvt.rn.f16x2.f32 %0, %1, %2;" : "=r"(r) : "f"(hi), "f"(lo));
    return r;
}
__device__ __forceinline__ void mmaF16(float* c,
                                       uint32_t a0, uint32_t a1, uint32_t a2, uint32_t a3,
                                       uint32_t b0, uint32_t b1) {
    asm volatile(
        "mma.sync.aligned.m16n8k16.row.col.f32.f16.f16.f32 "
        "{%0,%1,%2,%3}, {%4,%5,%6,%7}, {%8,%9}, {%0,%1,%2,%3};"
        : "+f"(c[0]), "+f"(c[1]), "+f"(c[2]), "+f"(c[3])
        : "r"(a0), "r"(a1), "r"(a2), "r"(a3), "r"(b0), "r"(b1));
}
__device__ __forceinline__ uint32_t tf(float x) {
    uint32_t r;
    asm("cvt.rna.tf32.f32 %0, %1;" : "=r"(r) : "f"(x));
    return r;
}
__device__ __forceinline__ void mmaTF32(float* c,
                                        uint32_t a0, uint32_t a1, uint32_t a2, uint32_t a3,
                                        uint32_t b0, uint32_t b1) {
    asm volatile(
        "mma.sync.aligned.m16n8k8.row.col.f32.tf32.tf32.f32 "
        "{%0,%1,%2,%3}, {%4,%5,%6,%7}, {%8,%9}, {%0,%1,%2,%3};"
        : "+f"(c[0]), "+f"(c[1]), "+f"(c[2]), "+f"(c[3])
        : "r"(a0), "r"(a1), "r"(a2), "r"(a3), "r"(b0), "r"(b1));
}
__device__ __forceinline__ float silu1(float x) {
    return x / (1.f + __expf(-x));
}

// ---------------- prep: rmsnorm(x)->y (blocks 0..15) + zero/seed (rest) ----------------
__global__ void prep(const float* __restrict__ x, const float* __restrict__ w) {
    if (blockIdx.x < 16) {
        int t = blockIdx.x;
        const float* row = x + (size_t)t * HIDDEN;
        float s = 0.f;
        for (int i = threadIdx.x; i < HIDDEN; i += 256) { float v = row[i]; s += v * v; }
        __shared__ float red[8];
        for (int o = 16; o > 0; o >>= 1) s += __shfl_xor_sync(0xffffffffu, s, o);
        if ((threadIdx.x & 31) == 0) red[threadIdx.x >> 5] = s;
        __syncthreads();
        float tot = 0.f;
#pragma unroll
        for (int i = 0; i < 8; i++) tot += red[i];
        float r = rsqrtf(tot / (float)HIDDEN + RMS_EPS);
        for (int i = threadIdx.x; i < HIDDEN; i += 256)
            g_y[(size_t)t * HIDDEN + i] = row[i] * r * w[i];
    } else {
        int i = (blockIdx.x - 16) * 256 + threadIdx.x;
        if (i < T_NEW * INTER) { g_gate[i] = 0.f; g_up[i] = 0.f; }
        if (i < T_NEW * NH * HD) { g_q[i] = 0.f; g_attnout[i] = 0.f; }
        if (i < T_NEW * NKV * HD) { g_k[i] = 0.f; g_v[i] = 0.f; }
        if (i < T_NEW * HIDDEN)  { g_h[i] = x[i]; }
    }
}

// ---------------- rmsnorm per token (optional raw copy to cp) ----------------
__global__ void rmsnorm16(const float* __restrict__ x, const float* __restrict__ w,
                          float* __restrict__ y, float* __restrict__ cp, int D) {
    int t = blockIdx.x;
    const float* row = x + (size_t)t * D;
    float s = 0.f;
    for (int i = threadIdx.x; i < D; i += 256) { float v = row[i]; s += v * v; }
    __shared__ float red[8];
    for (int o = 16; o > 0; o >>= 1) s += __shfl_xor_sync(0xffffffffu, s, o);
    if ((threadIdx.x & 31) == 0) red[threadIdx.x >> 5] = s;
    __syncthreads();
    float tot = 0.f;
#pragma unroll
    for (int i = 0; i < 8; i++) tot += red[i];
    float r = rsqrtf(tot / (float)D + RMS_EPS);
    for (int i = threadIdx.x; i < D; i += 256) {
        float v = row[i];
        y[(size_t)t * D + i] = v * r * w[i];
        if (cp) cp[(size_t)t * D + i] = v;
    }
}

// =============================================================
// mmaProj: fp16 smem-staged mma GEMM, software-pipelined.
// 128 threads: 128 weight rows x 16 tokens, K-chunk 32 floats.
// Small blocks -> 3-6 co-resident per SM for latency hiding.
// out[t][n] += sum_k act[t][k] * W[n][k]; if act2: act := silu(act)*act2.
// =============================================================
__global__ void __launch_bounds__(128)
mmaProj(const float* __restrict__ act, const float* __restrict__ act2,
        const float* __restrict__ W0, const float* __restrict__ W1,
        const float* __restrict__ W2,
        float* __restrict__ O0, float* __restrict__ O1, float* __restrict__ O2,
        int ldo0, int ldo1, int ldo2, int nb1, int nb2,
        int K, int klen) {
    __shared__ uint32_t sw[128][PROW];
    __shared__ uint32_t sa[16][PROW];

    const int tid = threadIdx.x;
    const int wid = tid >> 5;
    const int lane = tid & 31;
    const int g = blockIdx.x * 128;

    const float* W; float* O; int ldo, nloc;
    if (g >= nb2)      { W = W2; O = O2; ldo = ldo2; nloc = g - nb2; }
    else if (g >= nb1) { W = W1; O = O1; ldo = ldo1; nloc = g - nb1; }
    else               { W = W0; O = O0; ldo = ldo0; nloc = g; }

    const int kbeg = blockIdx.z * klen;
    const int kq = lane & 3;
    const int rsel = lane >> 2;
    const int rw = wid * 32;

    const int srow = tid >> 3;            // act row
    const int scol = (tid & 7) * 4;       // act float col

    float c[4][4];
#pragma unroll
    for (int j = 0; j < 4; j++)
#pragma unroll
        for (int i = 0; i < 4; i++) c[j][i] = 0.f;

    uint4 wq[4];
    uint32_t aq0 = 0, aq1 = 0;

    // prologue pack (chunk 0): 128 rows x 32 floats = 512 8-float packs
#pragma unroll
    for (int i = 0; i < 4; i++) {
        int u = tid + i * 128;
        int r = u >> 2, kc = (u & 3) * 8;
        const float* p = W + (long)(nloc + r) * K + kbeg + kc;
        float4 f0 = *(const float4*)p;
        float4 f1 = *(const float4*)(p + 4);
        wq[i] = make_uint4(h2(f0.x, f0.y), h2(f0.z, f0.w),
                           h2(f1.x, f1.y), h2(f1.z, f1.w));
    }
    {
        float4 av = *(const float4*)(act + (long)srow * K + kbeg + scol);
        if (act2) {
            float4 u = *(const float4*)(act2 + (long)srow * K + kbeg + scol);
            av = make_float4(silu1(av.x) * u.x, silu1(av.y) * u.y,
                             silu1(av.z) * u.z, silu1(av.w) * u.w);
        }
        aq0 = h2(av.x, av.y); aq1 = h2(av.z, av.w);
    }

    const int nchunks = klen >> 5;
    for (int ch = 0; ch < nchunks; ++ch) {
        __syncthreads();
#pragma unroll
        for (int i = 0; i < 4; i++) {
            int u = tid + i * 128;
            int r = u >> 2, kp = (u & 3) * 4;
            *(uint4*)&sw[r][kp] = wq[i];
        }
        sa[srow][(scol >> 1)] = aq0;
        sa[srow][(scol >> 1) + 1] = aq1;
        __syncthreads();

        if (ch + 1 < nchunks) {
            const int k0 = kbeg + (ch + 1) * 32;
#pragma unroll
            for (int i = 0; i < 4; i++) {
                int u = tid + i * 128;
                int r = u >> 2, kc = (u & 3) * 8;
                const float* p = W + (long)(nloc + r) * K + k0 + kc;
                float4 f0 = *(const float4*)p;
                float4 f1 = *(const float4*)(p + 4);
                wq[i] = make_uint4(h2(f0.x, f0.y), h2(f0.z, f0.w),
                                   h2(f1.x, f1.y), h2(f1.z, f1.w));
            }
            {
                float4 av = *(const float4*)(act + (long)srow * K + k0 + scol);
                if (act2) {
                    float4 u = *(const float4*)(act2 + (long)srow * K + k0 + scol);
                    av = make_float4(silu1(av.x) * u.x, silu1(av.y) * u.y,
                                     silu1(av.z) * u.z, silu1(av.w) * u.w);
                }
                aq0 = h2(av.x, av.y); aq1 = h2(av.z, av.w);
            }
        }

#pragma unroll
        for (int s = 0; s < 2; s++) {
            const int b8 = s * 8;
            uint32_t a0 = sa[rsel][b8 + kq];
            uint32_t a1 = sa[rsel + 8][b8 + kq];
            uint32_t a2 = sa[rsel][b8 + kq + 4];
            uint32_t a3 = sa[rsel + 8][b8 + kq + 4];
#pragma unroll
            for (int j = 0; j < 4; j++) {
                uint32_t b0 = sw[rw + j * 8 + rsel][b8 + kq];
                uint32_t b1 = sw[rw + j * 8 + rsel][b8 + kq + 4];
                mmaF16(c[j], a0, a1, a2, a3, b0, b1);
            }
        }
    }

    const int t0 = lane >> 2, t1 = t0 + 8;
    const int ncol = (lane & 3) * 2;
#pragma unroll
    for (int j = 0; j < 4; j++) {
        int n = nloc + rw + j * 8 + ncol;
        atomicAdd(O + (long)t0 * ldo + n,     c[j][0]);
        atomicAdd(O + (long)t0 * ldo + n + 1, c[j][1]);
        atomicAdd(O + (long)t1 * ldo + n,     c[j][2]);
        atomicAdd(O + (long)t1 * ldo + n + 1, c[j][3]);
    }
}

// =============================================================
// scoresMMA: GQA-batched fp16. 128 threads: 128 key-rows x 64 q-rows
// (4 heads x 16 tokens sharing a kv head). Grid (TFULL/128, NKV).
// =============================================================
__global__ void __launch_bounds__(128)
scoresMMA(const float* __restrict__ q,
          const float* __restrict__ kc_, const float* __restrict__ kn,
          const float* __restrict__ mask,
          float* __restrict__ scores, float scale) {
    __shared__ uint32_t sw[128][PROW];
    __shared__ uint32_t sa[64][PROW];

    const int tid = threadIdx.x;
    const int wid = tid >> 5;
    const int lane = tid & 31;
    const int kvh = blockIdx.y;
    const int h0 = kvh * 4;
    const int nbase = blockIdx.x * 128;

    const int kq = lane & 3;
    const int rsel = lane >> 2;
    const int rw = wid * 32;

    float c[4][4][4];
#pragma unroll
    for (int hh = 0; hh < 4; hh++)
#pragma unroll
        for (int j = 0; j < 4; j++)
#pragma unroll
            for (int i = 0; i < 4; i++) c[hh][j][i] = 0.f;

    uint4 wq[4], aq[2];

    // prologue (chunk 0): K 128 rows x 32 fl = 512 packs; q 64 rows x 32 fl = 256 packs
#pragma unroll
    for (int i = 0; i < 4; i++) {
        int u = tid + i * 128;
        int r = u >> 2, kcf = (u & 3) * 8;
        int rg = nbase + r;
        const float* src = (rg < TC)
            ? kc_ + ((long)kvh * TC + rg) * HD
            : kn + ((long)kvh * T_NEW + (rg - TC)) * HD;
        float4 f0 = *(const float4*)(src + kcf);
        float4 f1 = *(const float4*)(src + kcf + 4);
        wq[i] = make_uint4(h2(f0.x, f0.y), h2(f0.z, f0.w),
                           h2(f1.x, f1.y), h2(f1.z, f1.w));
    }
#pragma unroll
    for (int i = 0; i < 2; i++) {
        int u = tid + i * 128;
        int row = u >> 2, kcf = (u & 3) * 8;
        int hh = row >> 4, t = row & 15;
        const float* src = q + ((long)t * NH + h0 + hh) * HD + kcf;
        float4 f0 = *(const float4*)src;
        float4 f1 = *(const float4*)(src + 4);
        aq[i] = make_uint4(h2(f0.x, f0.y), h2(f0.z, f0.w),
                           h2(f1.x, f1.y), h2(f1.z, f1.w));
    }

#pragma unroll 1
    for (int ch = 0; ch < 4; ++ch) {
        __syncthreads();
#pragma unroll
        for (int i = 0; i < 4; i++) {
            int u = tid + i * 128;
            int r = u >> 2, kp = (u & 3) * 4;
            *(uint4*)&sw[r][kp] = wq[i];
        }
#pragma unroll
        for (int i = 0; i < 2; i++) {
            int u = tid + i * 128;
            int row = u >> 2, kp = (u & 3) * 4;
            *(uint4*)&sa[row][kp] = aq[i];
        }
        __syncthreads();

        if (ch + 1 < 4) {
            const int k0 = (ch + 1) * 32;
#pragma unroll
            for (int i = 0; i < 4; i++) {
                int u = tid + i * 128;
                int r = u >> 2, kcf = (u & 3) * 8;
                int rg = nbase + r;
                const float* src = (rg < TC)
                    ? kc_ + ((long)kvh * TC + rg) * HD
                    : kn + ((long)kvh * T_NEW + (rg - TC)) * HD;
                float4 f0 = *(const float4*)(src + k0 + kcf);
                float4 f1 = *(const float4*)(src + k0 + kcf + 4);
                wq[i] = make_uint4(h2(f0.x, f0.y), h2(f0.z, f0.w),
                                   h2(f1.x, f1.y), h2(f1.z, f1.w));
            }
#pragma unroll
            for (int i = 0; i < 2; i++) {
                int u = tid + i * 128;
                int row = u >> 2, kcf = (u & 3) * 8;
                int hh = row >> 4, t = row & 15;
                const float* src = q + ((long)t * NH + h0 + hh) * HD + k0 + kcf;
                float4 f0 = *(const float4*)src;
                float4 f1 = *(const float4*)(src + 4);
                aq[i] = make_uint4(h2(f0.x, f0.y), h2(f0.z, f0.w),
                                   h2(f1.x, f1.y), h2(f1.z, f1.w));
            }
        }

#pragma unroll
        for (int s = 0; s < 2; s++) {
            const int b8 = s * 8;
            uint32_t a[4][4];
#pragma unroll
            for (int hh = 0; hh < 4; hh++) {
                a[hh][0] = sa[hh * 16 + rsel][b8 + kq];
                a[hh][1] = sa[hh * 16 + rsel + 8][b8 + kq];
                a[hh][2] = sa[hh * 16 + rsel][b8 + kq + 4];
                a[hh][3] = sa[hh * 16 + rsel + 8][b8 + kq + 4];
            }
#pragma unroll
            for (int j = 0; j < 4; j++) {
                uint32_t b0 = sw[rw + j * 8 + rsel][b8 + kq];
                uint32_t b1 = sw[rw + j * 8 + rsel][b8 + kq + 4];
#pragma unroll
                for (int hh = 0; hh < 4; hh++)
                    mmaF16(c[hh][j], a[hh][0], a[hh][1], a[hh][2], a[hh][3], b0, b1);
            }
        }
    }

    const int t0 = lane >> 2, t1 = t0 + 8;
    const int ncol = (lane & 3) * 2;
#pragma unroll
    for (int hh = 0; hh < 4; hh++) {
        float* sh = scores + (long)(h0 + hh) * T_NEW * TFULL;
#pragma unroll
        for (int j = 0; j < 4; j++) {
            int n = nbase + rw + j * 8 + ncol;
            float2 v0 = make_float2(c[hh][j][0] * scale + mask[t0 * TFULL + n],
                                    c[hh][j][1] * scale + mask[t0 * TFULL + n + 1]);
            float2 v1 = make_float2(c[hh][j][2] * scale + mask[t1 * TFULL + n],
                                    c[hh][j][3] * scale + mask[t1 * TFULL + n + 1]);
            *(float2*)(sh + (long)t0 * TFULL + n) = v0;
            *(float2*)(sh + (long)t1 * TFULL + n) = v1;
        }
    }
}

// =============================================================
// pvMMA: GQA-batched tf32. Block 128 thr, m=64 (4 heads x 16 t),
// k-chunk 32 v-rows, split-K z=32 (128 rows per block), atomics.
// =============================================================
__global__ void __launch_bounds__(128)
pvMMA(const float* __restrict__ P,
      const float* __restrict__ vc, const float* __restrict__ vn,
      float* __restrict__ outA) {
    __shared__ uint32_t sv[32][VPAD];
    __shared__ uint32_t sa[64][APROW];

    const int tid = threadIdx.x;
    const int wid = tid >> 5;
    const int lane = tid & 31;
    const int kvh = blockIdx.y;
    const int h0 = kvh * 4;
    const int kbeg = blockIdx.z * 128;

    const int kq = lane & 3;
    const int rsel = lane >> 2;
    const int rw = wid * 32;

    float c[4][4][4];
#pragma unroll
    for (int hh = 0; hh < 4; hh++)
#pragma unroll
        for (int j = 0; j < 4; j++)
#pragma unroll
            for (int i = 0; i < 4; i++) c[hh][j][i] = 0.f;

    float4 wv[8], av[4];

#pragma unroll
    for (int i = 0; i < 8; i++) {
        int f = tid + i * 128;
        int vr = f >> 5, d0 = (f & 31) * 4;
        int rg = kbeg + vr;
        const float* src = (rg < TC)
            ? vc + ((long)kvh * TC + rg) * HD
            : vn + ((long)kvh * T_NEW + (rg - TC)) * HD;
        wv[i] = *(const float4*)(src + d0);
    }
#pragma unroll
    for (int i = 0; i < 4; i++) {
        int f = tid + i * 128;
        int row = f >> 3, cc = (f & 7) * 4;
        int hh = row >> 4, t = row & 15;
        av[i] = *(const float4*)(P + ((long)(h0 + hh) * T_NEW + t) * TFULL + kbeg + cc);
    }

#pragma unroll 1
    for (int ch = 0; ch < 4; ++ch) {
        __syncthreads();
#pragma unroll
        for (int i = 0; i < 8; i++) {
            int f = tid + i * 128;
            int vr = f >> 5, d0 = (f & 31) * 4;
            uint4 t = make_uint4(tf(wv[i].x), tf(wv[i].y), tf(wv[i].z), tf(wv[i].w));
            *(uint4*)&sv[vr][d0] = t;
        }
#pragma unroll
        for (int i = 0; i < 4; i++) {
            int f = tid + i * 128;
            int row = f >> 3, cc = (f & 7) * 4;
            uint4 t = make_uint4(tf(av[i].x), tf(av[i].y), tf(av[i].z), tf(av[i].w));
            *(uint4*)&sa[row][cc] = t;
        }
        __syncthreads();

        if (ch + 1 < 4) {
            const int kk0 = kbeg + (ch + 1) * 32;
#pragma unroll
            for (int i = 0; i < 8; i++) {
                int f = tid + i * 128;
                int vr = f >> 5, d0 = (f & 31) * 4;
                int rg = kk0 + vr;
                const float* src = (rg < TC)
                    ? vc + ((long)kvh * TC + rg) * HD
                    : vn + ((long)kvh * T_NEW + (rg - TC)) * HD;
                wv[i] = *(const float4*)(src + d0);
            }
#pragma unroll
            for (int i = 0; i < 4; i++) {
                int f = tid + i * 128;
                int row = f >> 3, cc = (f & 7) * 4;
                av[i] = *(const float4*)(P + ((long)(h0 + (row >> 4)) * T_NEW + (row & 15)) * TFULL + kk0 + cc);
            }
        }

#pragma unroll
        for (int s = 0; s < 4; s++) {
            const int s8 = s * 8;
            uint32_t a[4][4];
#pragma unroll
            for (int hh = 0; hh < 4; hh++) {
                a[hh][0] = sa[hh * 16 + rsel][s8 + kq];
                a[hh][1] = sa[hh * 16 + rsel + 8][s8 + kq];
                a[hh][2] = sa[hh * 16 + rsel][s8 + kq + 4];
                a[hh][3] = sa[hh * 16 + rsel + 8][s8 + kq + 4];
            }
#pragma unroll
            for (int j = 0; j < 4; j++) {
                uint32_t b0 = sv[s8 + kq][rw + j * 8 + rsel];
                uint32_t b1 = sv[s8 + kq + 4][rw + j * 8 + rsel];
#pragma unroll
                for (int hh = 0; hh < 4; hh++)
                    mmaTF32(c[hh][j], a[hh][0], a[hh][1], a[hh][2], a[hh][3], b0, b1);
            }
        }
    }

    const int t0 = lane >> 2, t1 = t0 + 8;
    const int ncol = (lane & 3) * 2;
#pragma unroll
    for (int hh = 0; hh < 4; hh++) {
        const long hb = (long)(h0 + hh) * HD;
#pragma unroll
        for (int j = 0; j < 4; j++) {
            int n = rw + j * 8 + ncol;
            float* o0 = outA + (long)t0 * (NH * HD) + hb + n;
            float* o1 = outA + (long)t1 * (NH * HD) + hb + n;
            atomicAdd(o0,     c[hh][j][0]);
            atomicAdd(o0 + 1, c[hh][j][1]);
            atomicAdd(o1,     c[hh][j][2]);
            atomicAdd(o1 + 1, c[hh][j][3]);
        }
    }
}

// ---------------- per-head rmsnorm + RoPE for q/k, and new_v copy ----------------
__global__ void qk_norm_rope(float* __restrict__ q, float* __restrict__ k,
                             const float* __restrict__ v,
                             const float* __restrict__ qw, const float* __restrict__ kw,
                             const float* __restrict__ cosr, const float* __restrict__ sinr,
                             float* __restrict__ outk, float* __restrict__ outv) {
    int t = blockIdx.x;
    int hh = blockIdx.y;
    int d = threadIdx.x;

    if (hh >= 40) {
        int h = hh - 40;
        outv[(size_t)(h * T_NEW + t) * HD + d] = v[(size_t)t * (NKV * HD) + h * HD + d];
        return;
    }

    __shared__ float sv[HD];
    __shared__ float red[4];
    float* row; const float* w;
    if (hh < 32) { row = q + (size_t)t * (NH * HD) + hh * HD; w = qw; }
    else         { row = k + (size_t)t * (NKV * HD) + (hh - 32) * HD; w = kw; }

    float val = row[d];
    float s = val * val;
    for (int o = 16; o > 0; o >>= 1) s += __shfl_xor_sync(0xffffffffu, s, o);
    if ((d & 31) == 0) red[d >> 5] = s;
    __syncthreads();
    float tot = red[0] + red[1] + red[2] + red[3];
    float r = rsqrtf(tot / 128.f + RMS_EPS);
    float xn = val * r * w[d];
    sv[d] = xn;
    __syncthreads();
    float rot = (d < 64) ? -sv[d + 64] : sv[d - 64];
    float o = xn * cosr[t * HD + d] + rot * sinr[t * HD + d];
    row[d] = o;
    if (hh >= 32) {
        int h = hh - 32;
        outk[(size_t)(h * T_NEW + t) * HD + d] = o;
    }
}

// ---------------- row softmax over TFULL ----------------
__global__ void softmax_rows(float* __restrict__ s) {
    int row = blockIdx.x;
    float* p = s + (size_t)row * TFULL;
    __shared__ float red[8];
    int tid = threadIdx.x;
    float m = -3.4e38f;
    for (int i = tid; i < TFULL; i += 256) m = fmaxf(m, p[i]);
    for (int o = 16; o > 0; o >>= 1) m = fmaxf(m, __shfl_xor_sync(0xffffffffu, m, o));
    if ((tid & 31) == 0) red[tid >> 5] = m;
    __syncthreads();
    float mm = red[0];
#pragma unroll
    for (int i = 1; i < 8; i++) mm = fmaxf(mm, red[i]);
    __syncthreads();
    float sum = 0.f;
    for (int i = tid; i < TFULL; i += 256) {
        float e = __expf(p[i] - mm);
        p[i] = e;
        sum += e;
    }
    for (int o = 16; o > 0; o >>= 1) sum += __shfl_xor_sync(0xffffffffu, sum, o);
    if ((tid & 31) == 0) red[tid >> 5] = sum;
    __syncthreads();
    float tot = 0.f;
#pragma unroll
    for (int i = 0; i < 8; i++) tot += red[i];
    float inv = 1.f / tot;
    for (int i = tid; i < TFULL; i += 256) p[i] *= inv;
}

static float* sym(const void* s) {
    void* p = nullptr;
    cudaGetSymbolAddress(&p, s);
    return (float*)p;
}

extern "C" void kernel_launch(void* const* d_in, const int* in_sizes, int n_in,
                              void* d_out, int out_size) {
    const float* x       = (const float*)d_in[0];
    const float* cos_q   = (const float*)d_in[1];
    const float* sin_q   = (const float*)d_in[2];
    const float* cache_k = (const float*)d_in[5];
    const float* cache_v = (const float*)d_in[6];
    const float* cmask   = (const float*)d_in[7];
    const float* ln1w    = (const float*)d_in[8];
    const float* ln2w    = (const float*)d_in[9];
    const float* qnw     = (const float*)d_in[10];
    const float* knw     = (const float*)d_in[11];
    const float* qw      = (const float*)d_in[12];
    const float* kw      = (const float*)d_in[13];
    const float* vw      = (const float*)d_in[14];
    const float* ow      = (const float*)d_in[15];
    const float* gw      = (const float*)d_in[16];
    const float* uw      = (const float*)d_in[17];
    const float* dw      = (const float*)d_in[18];
    float* out = (float*)d_out;
    float* out_k = out + T_NEW * HIDDEN;
    float* out_v = out_k + NKV * T_NEW * HD;

    static float *p_y = nullptr, *p_q, *p_k, *p_v, *p_scores, *p_attnout,
                 *p_h, *p_y2, *p_gate, *p_up;
    if (!p_y) {
        p_y = sym(g_y); p_q = sym(g_q); p_k = sym(g_k); p_v = sym(g_v);
        p_scores = sym(g_scores); p_attnout = sym(g_attnout);
        p_h = sym(g_h); p_y2 = sym(g_y2); p_gate = sym(g_gate); p_up = sym(g_up);
    }

    const float scale = 0.08838834764831845f; // 1/sqrt(128)
    const int BIG = 1 << 30;

    // 1) prep: rmsnorm1 (blocks 0-15) + zero atomic targets / seed h (rest)
    prep<<<16 + (T_NEW * INTER + 255) / 256, 256>>>(x, ln1w);

    // 2) fused QKV projection: q [0,4096), k [4096,5120), v [5120,6144)
    mmaProj<<<dim3(48, 1, 16), 128>>>(p_y, nullptr,
        qw, kw, vw, p_q, p_k, p_v,
        NH * HD, NKV * HD, NKV * HD,
        4096, 5120, HIDDEN, 160);

    // 3) per-head q/k rmsnorm + RoPE; writes new_k/new_v into d_out
    qk_norm_rope<<<dim3(T_NEW, 48), 128>>>(p_q, p_k, p_v, qnw, knw, cos_q, sin_q,
                                           out_k, out_v);

    // 4) scores (GQA-batched fp16 mma, fused scale+mask), 256 blocks
    scoresMMA<<<dim3(32, NKV), 128>>>(p_q, cache_k, out_k, cmask, p_scores, scale);

    // 5) softmax
    softmax_rows<<<NH * T_NEW, 256>>>(p_scores);

    // 6) attn_out = P @ V (GQA-batched tf32, split-K z=32, atomic), 256 blocks
    pvMMA<<<dim3(1, NKV, 32), 128>>>(p_scores, cache_v, out_v, p_attnout);

    // 7) O projection accumulates into h (pre-seeded with x)
    mmaProj<<<dim3(20, 1, 32), 128>>>(p_attnout, nullptr,
        ow, ow, ow, p_h, p_h, p_h,
        HIDDEN, HIDDEN, HIDDEN,
        BIG, BIG, NH * HD, 128);

    // 8) y2 = rmsnorm(h) * ln2; also copy h -> out (residual seed for down-proj)
    rmsnorm16<<<T_NEW, 256>>>(p_h, ln2w, p_y2, out, HIDDEN);

    // 9) fused gate/up: gate [0,9728), up [9728,19456)
    mmaProj<<<dim3(152, 1, 8), 128>>>(p_y2, nullptr,
        gw, uw, uw, p_gate, p_up, p_up,
        INTER, INTER, INTER,
        INTER, BIG, HIDDEN, 320);

    // 10) down projection with fused silu(gate)*up activation, accumulates into out
    mmaProj<<<dim3(20, 1, 38), 128>>>(p_gate, p_up,
        dw, dw, dw, out, out, out,
        HIDDEN, HIDDEN, HIDDEN,
        BIG, BIG, INTER, 256);
}

// round 15
// speedup vs baseline: 1.0199x; 1.0199x over previous
#include <cuda_runtime.h>
#include <cuda_bf16.h>
#include <cuda_fp16.h>
#include <math.h>
#include <stdint.h>

// ---------------- problem constants ----------------
#define T_NEW 16
#define HIDDEN 2560
#define INTER 9728
#define NH 32
#define NKV 8
#define HD 128
#define TC 4080
#define TFULL 4096
#define RMS_EPS 1e-6f
#define PROW 20      // half2 words per 32-float k-chunk row (16 + 4 pad)
#define SPLITS 32

// ---------------- scratch (device globals, no allocs) ----------------
__device__ float g_y[T_NEW * HIDDEN];
__device__ float g_q[T_NEW * NH * HD];
__device__ float g_k[T_NEW * NKV * HD];
__device__ float g_v[T_NEW * NKV * HD];
__device__ float g_attnout[T_NEW * NH * HD];
__device__ float g_h[T_NEW * HIDDEN];
__device__ float g_y2[T_NEW * HIDDEN];
__device__ float g_gate[T_NEW * INTER];
__device__ float g_up[T_NEW * INTER];
__device__ float g_po[NKV * SPLITS * 64 * 128];
__device__ float g_pml[NKV * SPLITS * 64 * 2];

// ---------------- fp16 mma helpers ----------------
__device__ __forceinline__ uint32_t h2(float lo, float hi) {
    uint32_t r;
    asm("cvt.rn.f16x2.f32 %0, %1, %2;" : "=r"(r) : "f"(hi), "f"(lo));
    return r;
}
__device__ __forceinline__ void mmaF16(float* c,
                                       uint32_t a0, uint32_t a1, uint32_t a2, uint32_t a3,
                                       uint32_t b0, uint32_t b1) {
    asm volatile(
        "mma.sync.aligned.m16n8k16.row.col.f32.f16.f16.f32 "
        "{%0,%1,%2,%3}, {%4,%5,%6,%7}, {%8,%9}, {%0,%1,%2,%3};"
        : "+f"(c[0]), "+f"(c[1]), "+f"(c[2]), "+f"(c[3])
        : "r"(a0), "r"(a1), "r"(a2), "r"(a3), "r"(b0), "r"(b1));
}
__device__ __forceinline__ float silu1(float x) {
    return x / (1.f + __expf(-x));
}

// ---------------- prep: rmsnorm(x)->y (blocks 0..15) + zero/seed (rest) ----------------
__global__ void prep(const float* __restrict__ x, const float* __restrict__ w) {
    if (blockIdx.x < 16) {
        int t = blockIdx.x;
        const float* row = x + (size_t)t * HIDDEN;
        float s = 0.f;
        for (int i = threadIdx.x; i < HIDDEN; i += 256) { float v = row[i]; s += v * v; }
        __shared__ float red[8];
        for (int o = 16; o > 0; o >>= 1) s += __shfl_xor_sync(0xffffffffu, s, o);
        if ((threadIdx.x & 31) == 0) red[threadIdx.x >> 5] = s;
        __syncthreads();
        float tot = 0.f;
#pragma unroll
        for (int i = 0; i < 8; i++) tot += red[i];
        float r = rsqrtf(tot / (float)HIDDEN + RMS_EPS);
        for (int i = threadIdx.x; i < HIDDEN; i += 256)
            g_y[(size_t)t * HIDDEN + i] = row[i] * r * w[i];
    } else {
        int i = (blockIdx.x - 16) * 256 + threadIdx.x;
        if (i < T_NEW * INTER) { g_gate[i] = 0.f; g_up[i] = 0.f; }
        if (i < T_NEW * NH * HD) { g_q[i] = 0.f; }
        if (i < T_NEW * NKV * HD) { g_k[i] = 0.f; g_v[i] = 0.f; }
        if (i < T_NEW * HIDDEN)  { g_h[i] = x[i]; }
    }
}

// ---------------- rmsnorm per token (optional raw copy to cp) ----------------
__global__ void rmsnorm16(const float* __restrict__ x, const float* __restrict__ w,
                          float* __restrict__ y, float* __restrict__ cp, int D) {
    int t = blockIdx.x;
    const float* row = x + (size_t)t * D;
    float s = 0.f;
    for (int i = threadIdx.x; i < D; i += 256) { float v = row[i]; s += v * v; }
    __shared__ float red[8];
    for (int o = 16; o > 0; o >>= 1) s += __shfl_xor_sync(0xffffffffu, s, o);
    if ((threadIdx.x & 31) == 0) red[threadIdx.x >> 5] = s;
    __syncthreads();
    float tot = 0.f;
#pragma unroll
    for (int i = 0; i < 8; i++) tot += red[i];
    float r = rsqrtf(tot / (float)D + RMS_EPS);
    for (int i = threadIdx.x; i < D; i += 256) {
        float v = row[i];
        y[(size_t)t * D + i] = v * r * w[i];
        if (cp) cp[(size_t)t * D + i] = v;
    }
}

// =============================================================
// mmaProj: fp16 smem-staged mma GEMM, software-pipelined (unchanged).
// 128 threads: 128 weight rows x 16 tokens, K-chunk 32 floats.
// =============================================================
__global__ void __launch_bounds__(128)
mmaProj(const float* __restrict__ act, const float* __restrict__ act2,
        const float* __restrict__ W0, const float* __restrict__ W1,
        const float* __restrict__ W2,
        float* __restrict__ O0, float* __restrict__ O1, float* __restrict__ O2,
        int ldo0, int ldo1, int ldo2, int nb1, int nb2,
        int K, int klen) {
    __shared__ uint32_t sw[128][PROW];
    __shared__ uint32_t sa[16][PROW];

    const int tid = threadIdx.x;
    const int wid = tid >> 5;
    const int lane = tid & 31;
    const int g = blockIdx.x * 128;

    const float* W; float* O; int ldo, nloc;
    if (g >= nb2)      { W = W2; O = O2; ldo = ldo2; nloc = g - nb2; }
    else if (g >= nb1) { W = W1; O = O1; ldo = ldo1; nloc = g - nb1; }
    else               { W = W0; O = O0; ldo = ldo0; nloc = g; }

    const int kbeg = blockIdx.z * klen;
    const int kq = lane & 3;
    const int rsel = lane >> 2;
    const int rw = wid * 32;

    const int srow = tid >> 3;
    const int scol = (tid & 7) * 4;

    float c[4][4];
#pragma unroll
    for (int j = 0; j < 4; j++)
#pragma unroll
        for (int i = 0; i < 4; i++) c[j][i] = 0.f;

    uint4 wq[4];
    uint32_t aq0 = 0, aq1 = 0;

#pragma unroll
    for (int i = 0; i < 4; i++) {
        int u = tid + i * 128;
        int r = u >> 2, kc = (u & 3) * 8;
        const float* p = W + (long)(nloc + r) * K + kbeg + kc;
        float4 f0 = *(const float4*)p;
        float4 f1 = *(const float4*)(p + 4);
        wq[i] = make_uint4(h2(f0.x, f0.y), h2(f0.z, f0.w),
                           h2(f1.x, f1.y), h2(f1.z, f1.w));
    }
    {
        float4 av = *(const float4*)(act + (long)srow * K + kbeg + scol);
        if (act2) {
            float4 u = *(const float4*)(act2 + (long)srow * K + kbeg + scol);
            av = make_float4(silu1(av.x) * u.x, silu1(av.y) * u.y,
                             silu1(av.z) * u.z, silu1(av.w) * u.w);
        }
        aq0 = h2(av.x, av.y); aq1 = h2(av.z, av.w);
    }

    const int nchunks = klen >> 5;
    for (int ch = 0; ch < nchunks; ++ch) {
        __syncthreads();
#pragma unroll
        for (int i = 0; i < 4; i++) {
            int u = tid + i * 128;
            int r = u >> 2, kp = (u & 3) * 4;
            *(uint4*)&sw[r][kp] = wq[i];
        }
        sa[srow][(scol >> 1)] = aq0;
        sa[srow][(scol >> 1) + 1] = aq1;
        __syncthreads();

        if (ch + 1 < nchunks) {
            const int k0 = kbeg + (ch + 1) * 32;
#pragma unroll
            for (int i = 0; i < 4; i++) {
                int u = tid + i * 128;
                int r = u >> 2, kc = (u & 3) * 8;
                const float* p = W + (long)(nloc + r) * K + k0 + kc;
                float4 f0 = *(const float4*)p;
                float4 f1 = *(const float4*)(p + 4);
                wq[i] = make_uint4(h2(f0.x, f0.y), h2(f0.z, f0.w),
                                   h2(f1.x, f1.y), h2(f1.z, f1.w));
            }
            {
                float4 av = *(const float4*)(act + (long)srow * K + k0 + scol);
                if (act2) {
                    float4 u = *(const float4*)(act2 + (long)srow * K + k0 + scol);
                    av = make_float4(silu1(av.x) * u.x, silu1(av.y) * u.y,
                                     silu1(av.z) * u.z, silu1(av.w) * u.w);
                }
                aq0 = h2(av.x, av.y); aq1 = h2(av.z, av.w);
            }
        }

#pragma unroll
        for (int s = 0; s < 2; s++) {
            const int b8 = s * 8;
            uint32_t a0 = sa[rsel][b8 + kq];
            uint32_t a1 = sa[rsel + 8][b8 + kq];
            uint32_t a2 = sa[rsel][b8 + kq + 4];
            uint32_t a3 = sa[rsel + 8][b8 + kq + 4];
#pragma unroll
            for (int j = 0; j < 4; j++) {
                uint32_t b0 = sw[rw + j * 8 + rsel][b8 + kq];
                uint32_t b1 = sw[rw + j * 8 + rsel][b8 + kq + 4];
                mmaF16(c[j], a0, a1, a2, a3, b0, b1);
            }
        }
    }

    const int t0 = lane >> 2, t1 = t0 + 8;
    const int ncol = (lane & 3) * 2;
#pragma unroll
    for (int j = 0; j < 4; j++) {
        int n = nloc + rw + j * 8 + ncol;
        atomicAdd(O + (long)t0 * ldo + n,     c[j][0]);
        atomicAdd(O + (long)t0 * ldo + n + 1, c[j][1]);
        atomicAdd(O + (long)t1 * ldo + n,     c[j][2]);
        atomicAdd(O + (long)t1 * ldo + n + 1, c[j][3]);
    }
}

// =============================================================
// flashAttn: fused scores + online softmax + P@V, split-KV.
// Grid (SPLITS, NKV), 128 thr. Block: m=64 (4 heads x 16 tokens),
// 128 KV rows in 4 chunks of 32. fp16 mma both GEMMs, fp32 m/l.
// Writes unnormalized partial O (64x128) + (m,l) per split.
// =============================================================
__global__ void __launch_bounds__(128)
flashAttn(const float* __restrict__ q,
          const float* __restrict__ kc_, const float* __restrict__ kn,
          const float* __restrict__ vc, const float* __restrict__ vn,
          float* __restrict__ po, float2* __restrict__ pml, float scale) {
    __shared__ uint32_t sQ[64][68];
    __shared__ uint32_t sK[32][68];
    __shared__ uint32_t sV[16][136];
    __shared__ uint32_t sP[64][20];
    __shared__ float sredM[4][64];
    __shared__ float sredS[4][64];

    const int tid = threadIdx.x;
    const int wid = tid >> 5, lane = tid & 31;
    const int kq = lane & 3, rsel = lane >> 2;
    const int rw = wid * 32;
    const int split = blockIdx.x, kvh = blockIdx.y;
    const int h0 = kvh * 4;

    // stage Q (64 rows x 128 d) as fp16 pairs, once
#pragma unroll
    for (int i = 0; i < 8; i++) {
        int u = tid + i * 128;
        int row = u >> 4, kc = (u & 15) * 8;
        int t = row & 15, hh = row >> 4;
        const float* src = q + ((long)t * NH + h0 + hh) * HD + kc;
        float4 f0 = *(const float4*)src, f1 = *(const float4*)(src + 4);
        int b = (u & 15) * 4;
        sQ[row][b + 0] = h2(f0.x, f0.y); sQ[row][b + 1] = h2(f0.z, f0.w);
        sQ[row][b + 2] = h2(f1.x, f1.y); sQ[row][b + 3] = h2(f1.z, f1.w);
    }

    float m_[4][2], l_[4][2], co[4][4][4];
#pragma unroll
    for (int hh = 0; hh < 4; hh++) {
        m_[hh][0] = -3.0e38f; m_[hh][1] = -3.0e38f;
        l_[hh][0] = 0.f; l_[hh][1] = 0.f;
#pragma unroll
        for (int j = 0; j < 4; j++)
#pragma unroll
            for (int i = 0; i < 4; i++) co[hh][j][i] = 0.f;
    }

#pragma unroll 1
    for (int ch = 0; ch < 4; ++ch) {
        const int kv0 = split * 128 + ch * 32;
        __syncthreads();   // previous PV reads of sV/sP done; sK reusable

        // K stage: 32 rows x 128 d
#pragma unroll
        for (int i = 0; i < 4; i++) {
            int u = tid + i * 128;
            int r = u >> 4, kc = (u & 15) * 8;
            int rg = kv0 + r;
            const float* src = (rg < TC)
                ? kc_ + ((long)kvh * TC + rg) * HD
                : kn + ((long)kvh * T_NEW + (rg - TC)) * HD;
            float4 f0 = *(const float4*)(src + kc), f1 = *(const float4*)(src + kc + 4);
            int b = (u & 15) * 4;
            sK[r][b + 0] = h2(f0.x, f0.y); sK[r][b + 1] = h2(f0.z, f0.w);
            sK[r][b + 2] = h2(f1.x, f1.y); sK[r][b + 3] = h2(f1.z, f1.w);
        }
        // V stage: row pairs packed (k, k+1) per half2
#pragma unroll
        for (int i = 0; i < 4; i++) {
            int u = tid + i * 128;
            int kp = u >> 5, d0 = (u & 31) * 4;
            int rg0 = kv0 + 2 * kp, rg1 = rg0 + 1;
            const float* s0 = (rg0 < TC)
                ? vc + ((long)kvh * TC + rg0) * HD
                : vn + ((long)kvh * T_NEW + (rg0 - TC)) * HD;
            const float* s1 = (rg1 < TC)
                ? vc + ((long)kvh * TC + rg1) * HD
                : vn + ((long)kvh * T_NEW + (rg1 - TC)) * HD;
            float4 a = *(const float4*)(s0 + d0), b = *(const float4*)(s1 + d0);
            sV[kp][d0 + 0] = h2(a.x, b.x); sV[kp][d0 + 1] = h2(a.y, b.y);
            sV[kp][d0 + 2] = h2(a.z, b.z); sV[kp][d0 + 3] = h2(a.w, b.w);
        }
        __syncthreads();

        // S = Q K^T; warp covers chunk cols [wid*8, wid*8+8)
        float cs[4][4];
#pragma unroll
        for (int hh = 0; hh < 4; hh++)
#pragma unroll
            for (int i = 0; i < 4; i++) cs[hh][i] = 0.f;
#pragma unroll
        for (int ks = 0; ks < 8; ks++) {
            uint32_t b0 = sK[wid * 8 + rsel][ks * 8 + kq];
            uint32_t b1 = sK[wid * 8 + rsel][ks * 8 + 4 + kq];
#pragma unroll
            for (int hh = 0; hh < 4; hh++) {
                uint32_t a0 = sQ[hh * 16 + rsel][ks * 8 + kq];
                uint32_t a1 = sQ[hh * 16 + rsel + 8][ks * 8 + kq];
                uint32_t a2 = sQ[hh * 16 + rsel][ks * 8 + 4 + kq];
                uint32_t a3 = sQ[hh * 16 + rsel + 8][ks * 8 + 4 + kq];
                mmaF16(cs[hh], a0, a1, a2, a3, b0, b1);
            }
        }

        // scale + causal mask + chunk row-max
        const int c0 = kv0 + wid * 8 + kq * 2;
#pragma unroll
        for (int hh = 0; hh < 4; hh++) {
            float s0 = cs[hh][0] * scale, s1 = cs[hh][1] * scale;
            float s2 = cs[hh][2] * scale, s3 = cs[hh][3] * scale;
            if (c0     - TC > rsel)     s0 -= 1.0e9f;
            if (c0 + 1 - TC > rsel)     s1 -= 1.0e9f;
            if (c0     - TC > rsel + 8) s2 -= 1.0e9f;
            if (c0 + 1 - TC > rsel + 8) s3 -= 1.0e9f;
            cs[hh][0] = s0; cs[hh][1] = s1; cs[hh][2] = s2; cs[hh][3] = s3;
            float mx0 = fmaxf(s0, s1), mx1 = fmaxf(s2, s3);
            mx0 = fmaxf(mx0, __shfl_xor_sync(0xffffffffu, mx0, 1));
            mx0 = fmaxf(mx0, __shfl_xor_sync(0xffffffffu, mx0, 2));
            mx1 = fmaxf(mx1, __shfl_xor_sync(0xffffffffu, mx1, 1));
            mx1 = fmaxf(mx1, __shfl_xor_sync(0xffffffffu, mx1, 2));
            if (kq == 0) {
                sredM[wid][hh * 16 + rsel] = mx0;
                sredM[wid][hh * 16 + rsel + 8] = mx1;
            }
        }
        __syncthreads();

        // online update: rescale O, compute P, row sums, stage P
#pragma unroll
        for (int hh = 0; hh < 4; hh++) {
            int r0 = hh * 16 + rsel, r1 = r0 + 8;
            float Mc0 = fmaxf(fmaxf(sredM[0][r0], sredM[1][r0]),
                              fmaxf(sredM[2][r0], sredM[3][r0]));
            float Mc1 = fmaxf(fmaxf(sredM[0][r1], sredM[1][r1]),
                              fmaxf(sredM[2][r1], sredM[3][r1]));
            float mn0 = fmaxf(m_[hh][0], Mc0), mn1 = fmaxf(m_[hh][1], Mc1);
            float f0 = __expf(m_[hh][0] - mn0), f1 = __expf(m_[hh][1] - mn1);
            m_[hh][0] = mn0; m_[hh][1] = mn1;
            l_[hh][0] *= f0; l_[hh][1] *= f1;
#pragma unroll
            for (int j = 0; j < 4; j++) {
                co[hh][j][0] *= f0; co[hh][j][1] *= f0;
                co[hh][j][2] *= f1; co[hh][j][3] *= f1;
            }
            float p0 = __expf(cs[hh][0] - mn0), p1 = __expf(cs[hh][1] - mn0);
            float p2 = __expf(cs[hh][2] - mn1), p3 = __expf(cs[hh][3] - mn1);
            float su0 = p0 + p1, su1 = p2 + p3;
            su0 += __shfl_xor_sync(0xffffffffu, su0, 1);
            su0 += __shfl_xor_sync(0xffffffffu, su0, 2);
            su1 += __shfl_xor_sync(0xffffffffu, su1, 1);
            su1 += __shfl_xor_sync(0xffffffffu, su1, 2);
            if (kq == 0) { sredS[wid][r0] = su0; sredS[wid][r1] = su1; }
            sP[r0][wid * 4 + kq] = h2(p0, p1);
            sP[r1][wid * 4 + kq] = h2(p2, p3);
        }
        __syncthreads();

#pragma unroll
        for (int hh = 0; hh < 4; hh++) {
            int r0 = hh * 16 + rsel, r1 = r0 + 8;
            l_[hh][0] += sredS[0][r0] + sredS[1][r0] + sredS[2][r0] + sredS[3][r0];
            l_[hh][1] += sredS[0][r1] + sredS[1][r1] + sredS[2][r1] + sredS[3][r1];
        }

        // O += P @ V ; warp covers d cols [wid*32, wid*32+32)
#pragma unroll
        for (int ks = 0; ks < 2; ks++) {
#pragma unroll
            for (int j = 0; j < 4; j++) {
                uint32_t b0 = sV[ks * 8 + kq][rw + j * 8 + rsel];
                uint32_t b1 = sV[ks * 8 + 4 + kq][rw + j * 8 + rsel];
#pragma unroll
                for (int hh = 0; hh < 4; hh++) {
                    uint32_t a0 = sP[hh * 16 + rsel][ks * 8 + kq];
                    uint32_t a1 = sP[hh * 16 + rsel + 8][ks * 8 + kq];
                    uint32_t a2 = sP[hh * 16 + rsel][ks * 8 + 4 + kq];
                    uint32_t a3 = sP[hh * 16 + rsel + 8][ks * 8 + 4 + kq];
                    mmaF16(co[hh][j], a0, a1, a2, a3, b0, b1);
                }
            }
        }
    }

    // write partial O (unnormalized) + (m, l)
    const long pbase = ((long)kvh * SPLITS + split) * 64;
#pragma unroll
    for (int hh = 0; hh < 4; hh++) {
        int r0 = hh * 16 + rsel, r1 = r0 + 8;
#pragma unroll
        for (int j = 0; j < 4; j++) {
            int d = rw + j * 8 + kq * 2;
            *(float2*)(po + (pbase + r0) * 128 + d) = make_float2(co[hh][j][0], co[hh][j][1]);
            *(float2*)(po + (pbase + r1) * 128 + d) = make_float2(co[hh][j][2], co[hh][j][3]);
        }
        if (wid == 0 && kq == 0) {
            pml[pbase + r0] = make_float2(m_[hh][0], l_[hh][0]);
            pml[pbase + r1] = make_float2(m_[hh][1], l_[hh][1]);
        }
    }
}

// =============================================================
// combineAttn: merge SPLITS partials -> g_attnout. Grid 512, 128 thr.
// =============================================================
__global__ void __launch_bounds__(128)
combineAttn(const float* __restrict__ po, const float2* __restrict__ pml,
            float* __restrict__ outA) {
    int kvh = blockIdx.x >> 6;
    int row = blockIdx.x & 63;
    int tid = threadIdx.x;
    __shared__ float sm[SPLITS], sl[SPLITS];
    if (tid < SPLITS) {
        float2 ml = pml[((long)kvh * SPLITS + tid) * 64 + row];
        sm[tid] = ml.x; sl[tid] = ml.y;
    }
    __syncthreads();
    float M = -3.4e38f;
#pragma unroll
    for (int s = 0; s < SPLITS; s++) M = fmaxf(M, sm[s]);
    float den = 0.f, acc = 0.f;
#pragma unroll 4
    for (int s = 0; s < SPLITS; s++) {
        float wgt = __expf(sm[s] - M);
        den += wgt * sl[s];
        acc += wgt * po[(((long)kvh * SPLITS + s) * 64 + row) * 128 + tid];
    }
    int t = row & 15, hh = row >> 4;
    outA[(long)t * (NH * HD) + (kvh * 4 + hh) * HD + tid] = acc / den;
}

// ---------------- per-head rmsnorm + RoPE for q/k, and new_v copy ----------------
__global__ void qk_norm_rope(float* __restrict__ q, float* __restrict__ k,
                             const float* __restrict__ v,
                             const float* __restrict__ qw, const float* __restrict__ kw,
                             const float* __restrict__ cosr, const float* __restrict__ sinr,
                             float* __restrict__ outk, float* __restrict__ outv) {
    int t = blockIdx.x;
    int hh = blockIdx.y;
    int d = threadIdx.x;

    if (hh >= 40) {
        int h = hh - 40;
        outv[(size_t)(h * T_NEW + t) * HD + d] = v[(size_t)t * (NKV * HD) + h * HD + d];
        return;
    }

    __shared__ float sv[HD];
    __shared__ float red[4];
    float* row; const float* w;
    if (hh < 32) { row = q + (size_t)t * (NH * HD) + hh * HD; w = qw; }
    else         { row = k + (size_t)t * (NKV * HD) + (hh - 32) * HD; w = kw; }

    float val = row[d];
    float s = val * val;
    for (int o = 16; o > 0; o >>= 1) s += __shfl_xor_sync(0xffffffffu, s, o);
    if ((d & 31) == 0) red[d >> 5] = s;
    __syncthreads();
    float tot = red[0] + red[1] + red[2] + red[3];
    float r = rsqrtf(tot / 128.f + RMS_EPS);
    float xn = val * r * w[d];
    sv[d] = xn;
    __syncthreads();
    float rot = (d < 64) ? -sv[d + 64] : sv[d - 64];
    float o = xn * cosr[t * HD + d] + rot * sinr[t * HD + d];
    row[d] = o;
    if (hh >= 32) {
        int h = hh - 32;
        outk[(size_t)(h * T_NEW + t) * HD + d] = o;
    }
}

static float* sym(const void* s) {
    void* p = nullptr;
    cudaGetSymbolAddress(&p, s);
    return (float*)p;
}

extern "C" void kernel_launch(void* const* d_in, const int* in_sizes, int n_in,
                              void* d_out, int out_size) {
    const float* x       = (const float*)d_in[0];
    const float* cos_q   = (const float*)d_in[1];
    const float* sin_q   = (const float*)d_in[2];
    const float* cache_k = (const float*)d_in[5];
    const float* cache_v = (const float*)d_in[6];
    const float* ln1w    = (const float*)d_in[8];
    const float* ln2w    = (const float*)d_in[9];
    const float* qnw     = (const float*)d_in[10];
    const float* knw     = (const float*)d_in[11];
    const float* qw      = (const float*)d_in[12];
    const float* kw      = (const float*)d_in[13];
    const float* vw      = (const float*)d_in[14];
    const float* ow      = (const float*)d_in[15];
    const float* gw      = (const float*)d_in[16];
    const float* uw      = (const float*)d_in[17];
    const float* dw      = (const float*)d_in[18];
    float* out = (float*)d_out;
    float* out_k = out + T_NEW * HIDDEN;
    float* out_v = out_k + NKV * T_NEW * HD;

    static float *p_y = nullptr, *p_q, *p_k, *p_v, *p_attnout,
                 *p_h, *p_y2, *p_gate, *p_up, *p_po, *p_pml;
    if (!p_y) {
        p_y = sym(g_y); p_q = sym(g_q); p_k = sym(g_k); p_v = sym(g_v);
        p_attnout = sym(g_attnout);
        p_h = sym(g_h); p_y2 = sym(g_y2); p_gate = sym(g_gate); p_up = sym(g_up);
        p_po = sym(g_po); p_pml = sym(g_pml);
    }

    const float scale = 0.08838834764831845f; // 1/sqrt(128)
    const int BIG = 1 << 30;

    // 1) prep: rmsnorm1 (blocks 0-15) + zero atomic targets / seed h (rest)
    prep<<<16 + (T_NEW * INTER + 255) / 256, 256>>>(x, ln1w);

    // 2) fused QKV projection: q [0,4096), k [4096,5120), v [5120,6144)
    mmaProj<<<dim3(48, 1, 16), 128>>>(p_y, nullptr,
        qw, kw, vw, p_q, p_k, p_v,
        NH * HD, NKV * HD, NKV * HD,
        4096, 5120, HIDDEN, 160);

    // 3) per-head q/k rmsnorm + RoPE; writes new_k/new_v into d_out
    qk_norm_rope<<<dim3(T_NEW, 48), 128>>>(p_q, p_k, p_v, qnw, knw, cos_q, sin_q,
                                           out_k, out_v);

    // 4) fused flash attention (scores + softmax + PV), split-KV
    flashAttn<<<dim3(SPLITS, NKV), 128>>>(p_q, cache_k, out_k, cache_v, out_v,
                                          p_po, (float2*)p_pml, scale);

    // 5) combine split partials -> attn_out
    combineAttn<<<NKV * 64, 128>>>(p_po, (const float2*)p_pml, p_attnout);

    // 6) O projection accumulates into h (pre-seeded with x)
    mmaProj<<<dim3(20, 1, 32), 128>>>(p_attnout, nullptr,
        ow, ow, ow, p_h, p_h, p_h,
        HIDDEN, HIDDEN, HIDDEN,
        BIG, BIG, NH * HD, 128);

    // 7) y2 = rmsnorm(h) * ln2; also copy h -> out (residual seed for down-proj)
    rmsnorm16<<<T_NEW, 256>>>(p_h, ln2w, p_y2, out, HIDDEN);

    // 8) fused gate/up: gate [0,9728), up [9728,19456)
    mmaProj<<<dim3(152, 1, 8), 128>>>(p_y2, nullptr,
        gw, uw, uw, p_gate, p_up, p_up,
        INTER, INTER, INTER,
        INTER, BIG, HIDDEN, 320);

    // 9) down projection with fused silu(gate)*up activation, accumulates into out
    mmaProj<<<dim3(20, 1, 38), 128>>>(p_gate, p_up,
        dw, dw, dw, out, out, out,
        HIDDEN, HIDDEN, HIDDEN,
        BIG, BIG, INTER, 256);
}

// round 17
// speedup vs baseline: 1.0321x; 1.0120x over previous
#include <cuda_runtime.h>
#include <cuda_bf16.h>
#include <cuda_fp16.h>
#include <math.h>
#include <stdint.h>

// ---------------- problem constants ----------------
#define T_NEW 16
#define HIDDEN 2560
#define INTER 9728
#define NH 32
#define NKV 8
#define HD 128
#define TC 4080
#define TFULL 4096
#define RMS_EPS 1e-6f
#define PROW 20      // half2 words per 32-float k-chunk row (16 + 4 pad)
#define SPLITS 32

// ---------------- scratch (device globals, no allocs) ----------------
__device__ float g_y[T_NEW * HIDDEN];
__device__ float g_q[T_NEW * NH * HD];
__device__ float g_k[T_NEW * NKV * HD];
__device__ float g_v[T_NEW * NKV * HD];
__device__ float g_attnout[T_NEW * NH * HD];
__device__ float g_h[T_NEW * HIDDEN];
__device__ float g_y2[T_NEW * HIDDEN];
__device__ float g_gate[T_NEW * INTER];
__device__ float g_up[T_NEW * INTER];
__device__ float g_po[NKV * SPLITS * 64 * 128];
__device__ float g_pml[NKV * SPLITS * 64 * 2];

// ---------------- fp16 mma helpers ----------------
__device__ __forceinline__ uint32_t h2(float lo, float hi) {
    uint32_t r;
    asm("cvt.rn.f16x2.f32 %0, %1, %2;" : "=r"(r) : "f"(hi), "f"(lo));
    return r;
}
__device__ __forceinline__ void mmaF16(float* c,
                                       uint32_t a0, uint32_t a1, uint32_t a2, uint32_t a3,
                                       uint32_t b0, uint32_t b1) {
    asm volatile(
        "mma.sync.aligned.m16n8k16.row.col.f32.f16.f16.f32 "
        "{%0,%1,%2,%3}, {%4,%5,%6,%7}, {%8,%9}, {%0,%1,%2,%3};"
        : "+f"(c[0]), "+f"(c[1]), "+f"(c[2]), "+f"(c[3])
        : "r"(a0), "r"(a1), "r"(a2), "r"(a3), "r"(b0), "r"(b1));
}
__device__ __forceinline__ float silu1(float x) {
    return x / (1.f + __expf(-x));
}

// ---------------- prep: rmsnorm(x)->y (blocks 0..15) + zero/seed (rest) ----------------
__global__ void prep(const float* __restrict__ x, const float* __restrict__ w) {
    if (blockIdx.x < 16) {
        int t = blockIdx.x;
        const float* row = x + (size_t)t * HIDDEN;
        float s = 0.f;
        for (int i = threadIdx.x; i < HIDDEN; i += 256) { float v = row[i]; s += v * v; }
        __shared__ float red[8];
        for (int o = 16; o > 0; o >>= 1) s += __shfl_xor_sync(0xffffffffu, s, o);
        if ((threadIdx.x & 31) == 0) red[threadIdx.x >> 5] = s;
        __syncthreads();
        float tot = 0.f;
#pragma unroll
        for (int i = 0; i < 8; i++) tot += red[i];
        float r = rsqrtf(tot / (float)HIDDEN + RMS_EPS);
        for (int i = threadIdx.x; i < HIDDEN; i += 256)
            g_y[(size_t)t * HIDDEN + i] = row[i] * r * w[i];
    } else {
        int i = (blockIdx.x - 16) * 256 + threadIdx.x;
        if (i < T_NEW * INTER) { g_gate[i] = 0.f; g_up[i] = 0.f; }
        if (i < T_NEW * NH * HD) { g_q[i] = 0.f; }
        if (i < T_NEW * NKV * HD) { g_k[i] = 0.f; g_v[i] = 0.f; }
        if (i < T_NEW * HIDDEN)  { g_h[i] = x[i]; }
    }
}

// ---------------- rmsnorm per token (optional raw copy to cp) ----------------
__global__ void rmsnorm16(const float* __restrict__ x, const float* __restrict__ w,
                          float* __restrict__ y, float* __restrict__ cp, int D) {
    int t = blockIdx.x;
    const float* row = x + (size_t)t * D;
    float s = 0.f;
    for (int i = threadIdx.x; i < D; i += 256) { float v = row[i]; s += v * v; }
    __shared__ float red[8];
    for (int o = 16; o > 0; o >>= 1) s += __shfl_xor_sync(0xffffffffu, s, o);
    if ((threadIdx.x & 31) == 0) red[threadIdx.x >> 5] = s;
    __syncthreads();
    float tot = 0.f;
#pragma unroll
    for (int i = 0; i < 8; i++) tot += red[i];
    float r = rsqrtf(tot / (float)D + RMS_EPS);
    for (int i = threadIdx.x; i < D; i += 256) {
        float v = row[i];
        y[(size_t)t * D + i] = v * r * w[i];
        if (cp) cp[(size_t)t * D + i] = v;
    }
}

// =============================================================
// mmaProj: fp16 smem-staged mma GEMM, software-pipelined (unchanged).
// 128 threads: 128 weight rows x 16 tokens, K-chunk 32 floats.
// =============================================================
__global__ void __launch_bounds__(128)
mmaProj(const float* __restrict__ act, const float* __restrict__ act2,
        const float* __restrict__ W0, const float* __restrict__ W1,
        const float* __restrict__ W2,
        float* __restrict__ O0, float* __restrict__ O1, float* __restrict__ O2,
        int ldo0, int ldo1, int ldo2, int nb1, int nb2,
        int K, int klen) {
    __shared__ uint32_t sw[128][PROW];
    __shared__ uint32_t sa[16][PROW];

    const int tid = threadIdx.x;
    const int wid = tid >> 5;
    const int lane = tid & 31;
    const int g = blockIdx.x * 128;

    const float* W; float* O; int ldo, nloc;
    if (g >= nb2)      { W = W2; O = O2; ldo = ldo2; nloc = g - nb2; }
    else if (g >= nb1) { W = W1; O = O1; ldo = ldo1; nloc = g - nb1; }
    else               { W = W0; O = O0; ldo = ldo0; nloc = g; }

    const int kbeg = blockIdx.z * klen;
    const int kq = lane & 3;
    const int rsel = lane >> 2;
    const int rw = wid * 32;

    const int srow = tid >> 3;
    const int scol = (tid & 7) * 4;

    float c[4][4];
#pragma unroll
    for (int j = 0; j < 4; j++)
#pragma unroll
        for (int i = 0; i < 4; i++) c[j][i] = 0.f;

    uint4 wq[4];
    uint32_t aq0 = 0, aq1 = 0;

#pragma unroll
    for (int i = 0; i < 4; i++) {
        int u = tid + i * 128;
        int r = u >> 2, kc = (u & 3) * 8;
        const float* p = W + (long)(nloc + r) * K + kbeg + kc;
        float4 f0 = *(const float4*)p;
        float4 f1 = *(const float4*)(p + 4);
        wq[i] = make_uint4(h2(f0.x, f0.y), h2(f0.z, f0.w),
                           h2(f1.x, f1.y), h2(f1.z, f1.w));
    }
    {
        float4 av = *(const float4*)(act + (long)srow * K + kbeg + scol);
        if (act2) {
            float4 u = *(const float4*)(act2 + (long)srow * K + kbeg + scol);
            av = make_float4(silu1(av.x) * u.x, silu1(av.y) * u.y,
                             silu1(av.z) * u.z, silu1(av.w) * u.w);
        }
        aq0 = h2(av.x, av.y); aq1 = h2(av.z, av.w);
    }

    const int nchunks = klen >> 5;
    for (int ch = 0; ch < nchunks; ++ch) {
        __syncthreads();
#pragma unroll
        for (int i = 0; i < 4; i++) {
            int u = tid + i * 128;
            int r = u >> 2, kp = (u & 3) * 4;
            *(uint4*)&sw[r][kp] = wq[i];
        }
        sa[srow][(scol >> 1)] = aq0;
        sa[srow][(scol >> 1) + 1] = aq1;
        __syncthreads();

        if (ch + 1 < nchunks) {
            const int k0 = kbeg + (ch + 1) * 32;
#pragma unroll
            for (int i = 0; i < 4; i++) {
                int u = tid + i * 128;
                int r = u >> 2, kc = (u & 3) * 8;
                const float* p = W + (long)(nloc + r) * K + k0 + kc;
                float4 f0 = *(const float4*)p;
                float4 f1 = *(const float4*)(p + 4);
                wq[i] = make_uint4(h2(f0.x, f0.y), h2(f0.z, f0.w),
                                   h2(f1.x, f1.y), h2(f1.z, f1.w));
            }
            {
                float4 av = *(const float4*)(act + (long)srow * K + k0 + scol);
                if (act2) {
                    float4 u = *(const float4*)(act2 + (long)srow * K + k0 + scol);
                    av = make_float4(silu1(av.x) * u.x, silu1(av.y) * u.y,
                                     silu1(av.z) * u.z, silu1(av.w) * u.w);
                }
                aq0 = h2(av.x, av.y); aq1 = h2(av.z, av.w);
            }
        }

#pragma unroll
        for (int s = 0; s < 2; s++) {
            const int b8 = s * 8;
            uint32_t a0 = sa[rsel][b8 + kq];
            uint32_t a1 = sa[rsel + 8][b8 + kq];
            uint32_t a2 = sa[rsel][b8 + kq + 4];
            uint32_t a3 = sa[rsel + 8][b8 + kq + 4];
#pragma unroll
            for (int j = 0; j < 4; j++) {
                uint32_t b0 = sw[rw + j * 8 + rsel][b8 + kq];
                uint32_t b1 = sw[rw + j * 8 + rsel][b8 + kq + 4];
                mmaF16(c[j], a0, a1, a2, a3, b0, b1);
            }
        }
    }

    const int t0 = lane >> 2, t1 = t0 + 8;
    const int ncol = (lane & 3) * 2;
#pragma unroll
    for (int j = 0; j < 4; j++) {
        int n = nloc + rw + j * 8 + ncol;
        atomicAdd(O + (long)t0 * ldo + n,     c[j][0]);
        atomicAdd(O + (long)t0 * ldo + n + 1, c[j][1]);
        atomicAdd(O + (long)t1 * ldo + n,     c[j][2]);
        atomicAdd(O + (long)t1 * ldo + n + 1, c[j][3]);
    }
}

// =============================================================
// flashAttn: fused scores + online softmax + P@V, split-KV.
// Grid (SPLITS, NKV), 128 thr. Block: m=64 (4 heads x 16 tokens),
// 128 KV rows in 4 chunks of 32. K/V prefetched into packed fp16
// registers one chunk ahead (loads overlap S-mma+softmax+PV).
// =============================================================
__global__ void __launch_bounds__(128)
flashAttn(const float* __restrict__ q,
          const float* __restrict__ kc_, const float* __restrict__ kn,
          const float* __restrict__ vc, const float* __restrict__ vn,
          float* __restrict__ po, float2* __restrict__ pml, float scale) {
    __shared__ uint32_t sQ[64][68];
    __shared__ uint32_t sK[32][68];
    __shared__ uint32_t sV[16][136];
    __shared__ uint32_t sP[64][20];
    __shared__ float sredM[4][64];
    __shared__ float sredS[4][64];

    const int tid = threadIdx.x;
    const int wid = tid >> 5, lane = tid & 31;
    const int kq = lane & 3, rsel = lane >> 2;
    const int rw = wid * 32;
    const int split = blockIdx.x, kvh = blockIdx.y;
    const int h0 = kvh * 4;

    // stage Q (64 rows x 128 d) as fp16 pairs, once
#pragma unroll
    for (int i = 0; i < 8; i++) {
        int u = tid + i * 128;
        int row = u >> 4, kc = (u & 15) * 8;
        int t = row & 15, hh = row >> 4;
        const float* src = q + ((long)t * NH + h0 + hh) * HD + kc;
        float4 f0 = *(const float4*)src, f1 = *(const float4*)(src + 4);
        int b = (u & 15) * 4;
        sQ[row][b + 0] = h2(f0.x, f0.y); sQ[row][b + 1] = h2(f0.z, f0.w);
        sQ[row][b + 2] = h2(f1.x, f1.y); sQ[row][b + 3] = h2(f1.z, f1.w);
    }

    float m_[4][2], l_[4][2], co[4][4][4];
#pragma unroll
    for (int hh = 0; hh < 4; hh++) {
        m_[hh][0] = -3.0e38f; m_[hh][1] = -3.0e38f;
        l_[hh][0] = 0.f; l_[hh][1] = 0.f;
#pragma unroll
        for (int j = 0; j < 4; j++)
#pragma unroll
            for (int i = 0; i < 4; i++) co[hh][j][i] = 0.f;
    }

    uint4 kq4[4], vq4[4];
    // prologue: pack chunk 0 K/V into registers
    {
        const int kv0 = split * 128;
#pragma unroll
        for (int i = 0; i < 4; i++) {
            int u = tid + i * 128;
            int r = u >> 4, kc = (u & 15) * 8;
            int rg = kv0 + r;
            const float* src = (rg < TC)
                ? kc_ + ((long)kvh * TC + rg) * HD
                : kn + ((long)kvh * T_NEW + (rg - TC)) * HD;
            float4 f0 = *(const float4*)(src + kc), f1 = *(const float4*)(src + kc + 4);
            kq4[i] = make_uint4(h2(f0.x, f0.y), h2(f0.z, f0.w),
                                h2(f1.x, f1.y), h2(f1.z, f1.w));
        }
#pragma unroll
        for (int i = 0; i < 4; i++) {
            int u = tid + i * 128;
            int kp = u >> 5, d0 = (u & 31) * 4;
            int rg0 = kv0 + 2 * kp, rg1 = rg0 + 1;
            const float* s0 = (rg0 < TC)
                ? vc + ((long)kvh * TC + rg0) * HD
                : vn + ((long)kvh * T_NEW + (rg0 - TC)) * HD;
            const float* s1 = (rg1 < TC)
                ? vc + ((long)kvh * TC + rg1) * HD
                : vn + ((long)kvh * T_NEW + (rg1 - TC)) * HD;
            float4 a = *(const float4*)(s0 + d0), b = *(const float4*)(s1 + d0);
            vq4[i] = make_uint4(h2(a.x, b.x), h2(a.y, b.y), h2(a.z, b.z), h2(a.w, b.w));
        }
    }

#pragma unroll 1
    for (int ch = 0; ch < 4; ++ch) {
        const int kv0 = split * 128 + ch * 32;
        __syncthreads();   // previous PV reads of sV/sP done

        // STS current chunk from registers
#pragma unroll
        for (int i = 0; i < 4; i++) {
            int u = tid + i * 128;
            int r = u >> 4, b = (u & 15) * 4;
            *(uint4*)&sK[r][b] = kq4[i];
        }
#pragma unroll
        for (int i = 0; i < 4; i++) {
            int u = tid + i * 128;
            int kp = u >> 5, d0 = (u & 31) * 4;
            *(uint4*)&sV[kp][d0] = vq4[i];
        }
        __syncthreads();

        // prefetch next chunk K/V (overlaps all compute below)
        if (ch + 1 < 4) {
            const int kn0 = kv0 + 32;
#pragma unroll
            for (int i = 0; i < 4; i++) {
                int u = tid + i * 128;
                int r = u >> 4, kc = (u & 15) * 8;
                int rg = kn0 + r;
                const float* src = (rg < TC)
                    ? kc_ + ((long)kvh * TC + rg) * HD
                    : kn + ((long)kvh * T_NEW + (rg - TC)) * HD;
                float4 f0 = *(const float4*)(src + kc), f1 = *(const float4*)(src + kc + 4);
                kq4[i] = make_uint4(h2(f0.x, f0.y), h2(f0.z, f0.w),
                                    h2(f1.x, f1.y), h2(f1.z, f1.w));
            }
#pragma unroll
            for (int i = 0; i < 4; i++) {
                int u = tid + i * 128;
                int kp = u >> 5, d0 = (u & 31) * 4;
                int rg0 = kn0 + 2 * kp, rg1 = rg0 + 1;
                const float* s0 = (rg0 < TC)
                    ? vc + ((long)kvh * TC + rg0) * HD
                    : vn + ((long)kvh * T_NEW + (rg0 - TC)) * HD;
                const float* s1 = (rg1 < TC)
                    ? vc + ((long)kvh * TC + rg1) * HD
                    : vn + ((long)kvh * T_NEW + (rg1 - TC)) * HD;
                float4 a = *(const float4*)(s0 + d0), b = *(const float4*)(s1 + d0);
                vq4[i] = make_uint4(h2(a.x, b.x), h2(a.y, b.y), h2(a.z, b.z), h2(a.w, b.w));
            }
        }

        // S = Q K^T; warp covers chunk cols [wid*8, wid*8+8)
        float cs[4][4];
#pragma unroll
        for (int hh = 0; hh < 4; hh++)
#pragma unroll
            for (int i = 0; i < 4; i++) cs[hh][i] = 0.f;
#pragma unroll
        for (int ks = 0; ks < 8; ks++) {
            uint32_t b0 = sK[wid * 8 + rsel][ks * 8 + kq];
            uint32_t b1 = sK[wid * 8 + rsel][ks * 8 + 4 + kq];
#pragma unroll
            for (int hh = 0; hh < 4; hh++) {
                uint32_t a0 = sQ[hh * 16 + rsel][ks * 8 + kq];
                uint32_t a1 = sQ[hh * 16 + rsel + 8][ks * 8 + kq];
                uint32_t a2 = sQ[hh * 16 + rsel][ks * 8 + 4 + kq];
                uint32_t a3 = sQ[hh * 16 + rsel + 8][ks * 8 + 4 + kq];
                mmaF16(cs[hh], a0, a1, a2, a3, b0, b1);
            }
        }

        // scale + causal mask + chunk row-max
        const int c0 = kv0 + wid * 8 + kq * 2;
#pragma unroll
        for (int hh = 0; hh < 4; hh++) {
            float s0 = cs[hh][0] * scale, s1 = cs[hh][1] * scale;
            float s2 = cs[hh][2] * scale, s3 = cs[hh][3] * scale;
            if (c0     - TC > rsel)     s0 -= 1.0e9f;
            if (c0 + 1 - TC > rsel)     s1 -= 1.0e9f;
            if (c0     - TC > rsel + 8) s2 -= 1.0e9f;
            if (c0 + 1 - TC > rsel + 8) s3 -= 1.0e9f;
            cs[hh][0] = s0; cs[hh][1] = s1; cs[hh][2] = s2; cs[hh][3] = s3;
            float mx0 = fmaxf(s0, s1), mx1 = fmaxf(s2, s3);
            mx0 = fmaxf(mx0, __shfl_xor_sync(0xffffffffu, mx0, 1));
            mx0 = fmaxf(mx0, __shfl_xor_sync(0xffffffffu, mx0, 2));
            mx1 = fmaxf(mx1, __shfl_xor_sync(0xffffffffu, mx1, 1));
            mx1 = fmaxf(mx1, __shfl_xor_sync(0xffffffffu, mx1, 2));
            if (kq == 0) {
                sredM[wid][hh * 16 + rsel] = mx0;
                sredM[wid][hh * 16 + rsel + 8] = mx1;
            }
        }
        __syncthreads();

        // online update: rescale O, compute P, row sums, stage P
#pragma unroll
        for (int hh = 0; hh < 4; hh++) {
            int r0 = hh * 16 + rsel, r1 = r0 + 8;
            float Mc0 = fmaxf(fmaxf(sredM[0][r0], sredM[1][r0]),
                              fmaxf(sredM[2][r0], sredM[3][r0]));
            float Mc1 = fmaxf(fmaxf(sredM[0][r1], sredM[1][r1]),
                              fmaxf(sredM[2][r1], sredM[3][r1]));
            float mn0 = fmaxf(m_[hh][0], Mc0), mn1 = fmaxf(m_[hh][1], Mc1);
            float f0 = __expf(m_[hh][0] - mn0), f1 = __expf(m_[hh][1] - mn1);
            m_[hh][0] = mn0; m_[hh][1] = mn1;
            l_[hh][0] *= f0; l_[hh][1] *= f1;
#pragma unroll
            for (int j = 0; j < 4; j++) {
                co[hh][j][0] *= f0; co[hh][j][1] *= f0;
                co[hh][j][2] *= f1; co[hh][j][3] *= f1;
            }
            float p0 = __expf(cs[hh][0] - mn0), p1 = __expf(cs[hh][1] - mn0);
            float p2 = __expf(cs[hh][2] - mn1), p3 = __expf(cs[hh][3] - mn1);
            float su0 = p0 + p1, su1 = p2 + p3;
            su0 += __shfl_xor_sync(0xffffffffu, su0, 1);
            su0 += __shfl_xor_sync(0xffffffffu, su0, 2);
            su1 += __shfl_xor_sync(0xffffffffu, su1, 1);
            su1 += __shfl_xor_sync(0xffffffffu, su1, 2);
            if (kq == 0) { sredS[wid][r0] = su0; sredS[wid][r1] = su1; }
            sP[r0][wid * 4 + kq] = h2(p0, p1);
            sP[r1][wid * 4 + kq] = h2(p2, p3);
        }
        __syncthreads();

#pragma unroll
        for (int hh = 0; hh < 4; hh++) {
            int r0 = hh * 16 + rsel, r1 = r0 + 8;
            l_[hh][0] += sredS[0][r0] + sredS[1][r0] + sredS[2][r0] + sredS[3][r0];
            l_[hh][1] += sredS[0][r1] + sredS[1][r1] + sredS[2][r1] + sredS[3][r1];
        }

        // O += P @ V ; warp covers d cols [wid*32, wid*32+32)
#pragma unroll
        for (int ks = 0; ks < 2; ks++) {
#pragma unroll
            for (int j = 0; j < 4; j++) {
                uint32_t b0 = sV[ks * 8 + kq][rw + j * 8 + rsel];
                uint32_t b1 = sV[ks * 8 + 4 + kq][rw + j * 8 + rsel];
#pragma unroll
                for (int hh = 0; hh < 4; hh++) {
                    uint32_t a0 = sP[hh * 16 + rsel][ks * 8 + kq];
                    uint32_t a1 = sP[hh * 16 + rsel + 8][ks * 8 + kq];
                    uint32_t a2 = sP[hh * 16 + rsel][ks * 8 + 4 + kq];
                    uint32_t a3 = sP[hh * 16 + rsel + 8][ks * 8 + 4 + kq];
                    mmaF16(co[hh][j], a0, a1, a2, a3, b0, b1);
                }
            }
        }
    }

    // write partial O (unnormalized) + (m, l)
    const long pbase = ((long)kvh * SPLITS + split) * 64;
#pragma unroll
    for (int hh = 0; hh < 4; hh++) {
        int r0 = hh * 16 + rsel, r1 = r0 + 8;
#pragma unroll
        for (int j = 0; j < 4; j++) {
            int d = rw + j * 8 + kq * 2;
            *(float2*)(po + (pbase + r0) * 128 + d) = make_float2(co[hh][j][0], co[hh][j][1]);
            *(float2*)(po + (pbase + r1) * 128 + d) = make_float2(co[hh][j][2], co[hh][j][3]);
        }
        if (wid == 0 && kq == 0) {
            pml[pbase + r0] = make_float2(m_[hh][0], l_[hh][0]);
            pml[pbase + r1] = make_float2(m_[hh][1], l_[hh][1]);
        }
    }
}

// =============================================================
// combineAttn: merge SPLITS partials -> g_attnout. Grid 512, 128 thr.
// =============================================================
__global__ void __launch_bounds__(128)
combineAttn(const float* __restrict__ po, const float2* __restrict__ pml,
            float* __restrict__ outA) {
    int kvh = blockIdx.x >> 6;
    int row = blockIdx.x & 63;
    int tid = threadIdx.x;
    __shared__ float sm[SPLITS], sl[SPLITS];
    if (tid < SPLITS) {
        float2 ml = pml[((long)kvh * SPLITS + tid) * 64 + row];
        sm[tid] = ml.x; sl[tid] = ml.y;
    }
    __syncthreads();
    float M = -3.4e38f;
#pragma unroll
    for (int s = 0; s < SPLITS; s++) M = fmaxf(M, sm[s]);
    float den = 0.f, acc = 0.f;
#pragma unroll 4
    for (int s = 0; s < SPLITS; s++) {
        float wgt = __expf(sm[s] - M);
        den += wgt * sl[s];
        acc += wgt * po[(((long)kvh * SPLITS + s) * 64 + row) * 128 + tid];
    }
    int t = row & 15, hh = row >> 4;
    outA[(long)t * (NH * HD) + (kvh * 4 + hh) * HD + tid] = acc / den;
}

// ---------------- per-head rmsnorm + RoPE for q/k, and new_v copy ----------------
__global__ void qk_norm_rope(float* __restrict__ q, float* __restrict__ k,
                             const float* __restrict__ v,
                             const float* __restrict__ qw, const float* __restrict__ kw,
                             const float* __restrict__ cosr, const float* __restrict__ sinr,
                             float* __restrict__ outk, float* __restrict__ outv) {
    int t = blockIdx.x;
    int hh = blockIdx.y;
    int d = threadIdx.x;

    if (hh >= 40) {
        int h = hh - 40;
        outv[(size_t)(h * T_NEW + t) * HD + d] = v[(size_t)t * (NKV * HD) + h * HD + d];
        return;
    }

    __shared__ float sv[HD];
    __shared__ float red[4];
    float* row; const float* w;
    if (hh < 32) { row = q + (size_t)t * (NH * HD) + hh * HD; w = qw; }
    else         { row = k + (size_t)t * (NKV * HD) + (hh - 32) * HD; w = kw; }

    float val = row[d];
    float s = val * val;
    for (int o = 16; o > 0; o >>= 1) s += __shfl_xor_sync(0xffffffffu, s, o);
    if ((d & 31) == 0) red[d >> 5] = s;
    __syncthreads();
    float tot = red[0] + red[1] + red[2] + red[3];
    float r = rsqrtf(tot / 128.f + RMS_EPS);
    float xn = val * r * w[d];
    sv[d] = xn;
    __syncthreads();
    float rot = (d < 64) ? -sv[d + 64] : sv[d - 64];
    float o = xn * cosr[t * HD + d] + rot * sinr[t * HD + d];
    row[d] = o;
    if (hh >= 32) {
        int h = hh - 32;
        outk[(size_t)(h * T_NEW + t) * HD + d] = o;
    }
}

static float* sym(const void* s) {
    void* p = nullptr;
    cudaGetSymbolAddress(&p, s);
    return (float*)p;
}

extern "C" void kernel_launch(void* const* d_in, const int* in_sizes, int n_in,
                              void* d_out, int out_size) {
    const float* x       = (const float*)d_in[0];
    const float* cos_q   = (const float*)d_in[1];
    const float* sin_q   = (const float*)d_in[2];
    const float* cache_k = (const float*)d_in[5];
    const float* cache_v = (const float*)d_in[6];
    const float* ln1w    = (const float*)d_in[8];
    const float* ln2w    = (const float*)d_in[9];
    const float* qnw     = (const float*)d_in[10];
    const float* knw     = (const float*)d_in[11];
    const float* qw      = (const float*)d_in[12];
    const float* kw      = (const float*)d_in[13];
    const float* vw      = (const float*)d_in[14];
    const float* ow      = (const float*)d_in[15];
    const float* gw      = (const float*)d_in[16];
    const float* uw      = (const float*)d_in[17];
    const float* dw      = (const float*)d_in[18];
    float* out = (float*)d_out;
    float* out_k = out + T_NEW * HIDDEN;
    float* out_v = out_k + NKV * T_NEW * HD;

    static float *p_y = nullptr, *p_q, *p_k, *p_v, *p_attnout,
                 *p_h, *p_y2, *p_gate, *p_up, *p_po, *p_pml;
    if (!p_y) {
        p_y = sym(g_y); p_q = sym(g_q); p_k = sym(g_k); p_v = sym(g_v);
        p_attnout = sym(g_attnout);
        p_h = sym(g_h); p_y2 = sym(g_y2); p_gate = sym(g_gate); p_up = sym(g_up);
        p_po = sym(g_po); p_pml = sym(g_pml);
    }

    const float scale = 0.08838834764831845f; // 1/sqrt(128)
    const int BIG = 1 << 30;

    // 1) prep: rmsnorm1 (blocks 0-15) + zero atomic targets / seed h (rest)
    prep<<<16 + (T_NEW * INTER + 255) / 256, 256>>>(x, ln1w);

    // 2) fused QKV projection: q [0,4096), k [4096,5120), v [5120,6144)
    mmaProj<<<dim3(48, 1, 16), 128>>>(p_y, nullptr,
        qw, kw, vw, p_q, p_k, p_v,
        NH * HD, NKV * HD, NKV * HD,
        4096, 5120, HIDDEN, 160);

    // 3) per-head q/k rmsnorm + RoPE; writes new_k/new_v into d_out
    qk_norm_rope<<<dim3(T_NEW, 48), 128>>>(p_q, p_k, p_v, qnw, knw, cos_q, sin_q,
                                           out_k, out_v);

    // 4) fused flash attention (scores + softmax + PV), split-KV, prefetched
    flashAttn<<<dim3(SPLITS, NKV), 128>>>(p_q, cache_k, out_k, cache_v, out_v,
                                          p_po, (float2*)p_pml, scale);

    // 5) combine split partials -> attn_out
    combineAttn<<<NKV * 64, 128>>>(p_po, (const float2*)p_pml, p_attnout);

    // 6) O projection accumulates into h (pre-seeded with x)
    mmaProj<<<dim3(20, 1, 32), 128>>>(p_attnout, nullptr,
        ow, ow, ow, p_h, p_h, p_h,
        HIDDEN, HIDDEN, HIDDEN,
        BIG, BIG, NH * HD, 128);

    // 7) y2 = rmsnorm(h) * ln2; also copy h -> out (residual seed for down-proj)
    rmsnorm16<<<T_NEW, 256>>>(p_h, ln2w, p_y2, out, HIDDEN);

    // 8) fused gate/up: gate [0,9728), up [9728,19456)
    mmaProj<<<dim3(152, 1, 8), 128>>>(p_y2, nullptr,
        gw, uw, uw, p_gate, p_up, p_up,
        INTER, INTER, INTER,
        INTER, BIG, HIDDEN, 320);

    // 9) down projection with fused silu(gate)*up activation, accumulates into out
    mmaProj<<<dim3(20, 1, 38), 128>>>(p_gate, p_up,
        dw, dw, dw, out, out, out,
        HIDDEN, HIDDEN, HIDDEN,
        BIG, BIG, INTER, 256);
}